// round 3
// baseline (speedup 1.0000x reference)
#include <cuda_runtime.h>
#include <math.h>
#include <stdint.h>

#define NN 8192
#define DD 64
#define SS 4096
#define BETA0 0.1f
#define BETA1 0.1f
#define EPS_C 1e-6f

#define CHUNK_F 2048                 // floats per chunk per row (8 KB)
#define CHUNK_B (CHUNK_F * 4)
#define NCHUNK (NN / CHUNK_F)        // 4 stages, all in flight
#define DYN_SMEM (NCHUNK * 2 * CHUNK_B)   // 64 KB

__device__ float g_Lsh;
__device__ float g_Ltr;
__device__ float g_sq;
__device__ float g_diag[NN];

// ---- fused: diag + smooth (blocks [0,1024)) and triplet hinge (blocks [1024,1536)) ----
__global__ void __launch_bounds__(256) prep_kernel(
    const float* __restrict__ emb_t,
    const float* __restrict__ emb_prev,
    const float* __restrict__ theta,
    const int* __restrict__ j_idx,
    const int* __restrict__ k_idx,
    const int* __restrict__ negj_idx) {
    int lane = threadIdx.x & 31;
    if (blockIdx.x < NN / 8) {
        int gw = blockIdx.x * 8 + (threadIdx.x >> 5);          // node row
        const float* th = theta    + (size_t)gw * DD;
        const float* et = emb_t    + (size_t)gw * DD;
        const float* ep = emb_prev + (size_t)gw * DD;
        float dsum = 0.f, ssum = 0.f;
        #pragma unroll
        for (int d = lane; d < DD; d += 32) {
            float e = et[d];
            dsum += th[d] * e;
            float df = e - ep[d];
            ssum += df * df;
        }
        #pragma unroll
        for (int o = 16; o; o >>= 1) {
            dsum += __shfl_down_sync(0xffffffffu, dsum, o);
            ssum += __shfl_down_sync(0xffffffffu, ssum, o);
        }
        if (lane == 0) {
            g_diag[gw] = dsum;
            atomicAdd(&g_sq, ssum);
        }
    } else {
        int s = (blockIdx.x - NN / 8) * 8 + (threadIdx.x >> 5); // sample
        int j = j_idx[s], k = k_idx[s], nj = negj_idx[s];
        const float* uj = emb_t + (size_t)j  * DD;
        const float* uk = emb_t + (size_t)k  * DD;
        const float* un = emb_t + (size_t)nj * DD;
        float pos = 0.f, neg = 0.f;
        #pragma unroll
        for (int d = lane; d < DD; d += 32) {
            float a = uj[d] - uk[d]; pos += a * a;
            float b = un[d] - uk[d]; neg += b * b;
        }
        #pragma unroll
        for (int o = 16; o; o >>= 1) {
            pos += __shfl_down_sync(0xffffffffu, pos, o);
            neg += __shfl_down_sync(0xffffffffu, neg, o);
        }
        if (lane == 0) {
            float h = pos - neg + 1.0f;
            if (h > 0.f) atomicAdd(&g_Lsh, h);
        }
    }
}

__device__ __forceinline__ float softplus_stable(float x) {
    return fmaxf(x, 0.f) + log1pf(expf(-fabsf(x)));
}

// ---- TMA bulk-copy + mbarrier helpers ----
__device__ __forceinline__ void mbar_init(uint32_t mbar, uint32_t count) {
    asm volatile("mbarrier.init.shared.b64 [%0], %1;" :: "r"(mbar), "r"(count) : "memory");
}
__device__ __forceinline__ void mbar_expect_tx(uint32_t mbar, uint32_t bytes) {
    asm volatile("mbarrier.arrive.expect_tx.shared.b64 _, [%0], %1;"
                 :: "r"(mbar), "r"(bytes) : "memory");
}
__device__ __forceinline__ void bulk_g2s(uint32_t dst_smem, const void* src_gmem,
                                         uint32_t bytes, uint32_t mbar) {
    asm volatile(
        "cp.async.bulk.shared::cluster.global.mbarrier::complete_tx::bytes "
        "[%0], [%1], %2, [%3];"
        :: "r"(dst_smem), "l"(src_gmem), "r"(bytes), "r"(mbar) : "memory");
}
__device__ __forceinline__ void mbar_wait(uint32_t mbar, uint32_t parity) {
    asm volatile(
        "{\n\t"
        ".reg .pred P1;\n\t"
        "WAIT_LOOP_%=:\n\t"
        "mbarrier.try_wait.parity.acquire.cta.shared::cta.b64 P1, [%0], %1, 0x989680;\n\t"
        "@P1 bra.uni WAIT_DONE_%=;\n\t"
        "bra.uni WAIT_LOOP_%=;\n\t"
        "WAIT_DONE_%=:\n\t"
        "}"
        :: "r"(mbar), "r"(parity) : "memory");
}

// (1 - P) contribution for one candidate common neighbor
__device__ __forceinline__ float cn_term(float a, float b, int l,
                                         const float* __restrict__ s_ui,
                                         const float* __restrict__ s_uj,
                                         const float* __restrict__ theta) {
    if (a > 0.f && b > 0.f) {
        const float4* th = (const float4*)(theta + (size_t)l * DD);
        float ti = 0.f, tj = 0.f;
        #pragma unroll
        for (int q = 0; q < DD / 4; q++) {
            float4 t = __ldg(th + q);
            ti += t.x * s_ui[4*q]   + t.y * s_ui[4*q+1]
                + t.z * s_ui[4*q+2] + t.w * s_ui[4*q+3];
            tj += t.x * s_uj[4*q]   + t.y * s_uj[4*q+1]
                + t.z * s_uj[4*q+2] + t.w * s_uj[4*q+3];
        }
        float dg = g_diag[l];
        float dot = a * (dg - ti) + b * (dg - tj);
        if (dot < -100.f) return 1.f;
        float P = 1.f / (1.f + expf(-dot));
        return 1.f - P;
    }
    return 1.f;
}

// L_tr: one block (256 threads) per sample; all 4 chunk-pairs TMA'd up-front
__global__ void __launch_bounds__(256) ltr_kernel(
    const float* __restrict__ emb_t,
    const float* __restrict__ theta,
    const float* __restrict__ adj,
    const int* __restrict__ j_idx,
    const int* __restrict__ k_idx,
    const int* __restrict__ i_idx,
    const int* __restrict__ cond) {

    extern __shared__ __align__(16) float sbuf[];        // [NCHUNK][2][CHUNK_F] = 64 KB
    __shared__ alignas(8) unsigned long long smbar[NCHUNK];
    __shared__ float s_ui[DD];
    __shared__ float s_uj[DD];
    __shared__ float s_red[8];
    __shared__ float s_tik, s_tjk;

    int s = blockIdx.x;
    int c = cond[s];
    if (c == -1) return;

    int i = i_idx[s], j = j_idx[s], k = k_idx[s];
    int tid = threadIdx.x;

    if (tid < DD)          s_ui[tid]      = emb_t[(size_t)i * DD + tid];
    else if (tid < 2*DD)   s_uj[tid - DD] = emb_t[(size_t)j * DD + (tid - DD)];

    uint32_t mb0 = (uint32_t)__cvta_generic_to_shared(&smbar[0]);
    if (c == 1 && tid == 0) {
        #pragma unroll
        for (int cc = 0; cc < NCHUNK; ++cc) mbar_init(mb0 + 8 * cc, 1);
        asm volatile("fence.proxy.async.shared::cta;" ::: "memory");
    }
    __syncthreads();

    float prodL = 1.f;
    if (c == 1) {
        const float* ri = adj + (size_t)i * NN;
        const float* rj = adj + (size_t)j * NN;
        uint32_t sb = (uint32_t)__cvta_generic_to_shared(sbuf);

        if (tid == 0) {
            #pragma unroll
            for (int cc = 0; cc < NCHUNK; ++cc) {
                uint32_t mb = mb0 + 8 * cc;
                uint32_t dst = sb + (uint32_t)cc * 2 * CHUNK_B;
                mbar_expect_tx(mb, 2 * CHUNK_B);
                bulk_g2s(dst,           ri + (size_t)cc * CHUNK_F, CHUNK_B, mb);
                bulk_g2s(dst + CHUNK_B, rj + (size_t)cc * CHUNK_F, CHUNK_B, mb);
            }
        }

        #pragma unroll
        for (int cc = 0; cc < NCHUNK; ++cc) {
            mbar_wait(mb0 + 8 * cc, 0);
            const float4* A = (const float4*)(sbuf + (size_t)cc * 2 * CHUNK_F);
            const float4* B = (const float4*)(sbuf + (size_t)cc * 2 * CHUNK_F + CHUNK_F);
            #pragma unroll
            for (int it = 0; it < CHUNK_F / 4 / 256; ++it) {   // 2 iterations
                int q = tid + it * 256;
                float4 a = A[q];
                float4 b = B[q];
                int l0 = cc * CHUNK_F + q * 4;
                prodL *= cn_term(a.x, b.x, l0 + 0, s_ui, s_uj, theta);
                prodL *= cn_term(a.y, b.y, l0 + 1, s_ui, s_uj, theta);
                prodL *= cn_term(a.z, b.z, l0 + 2, s_ui, s_uj, theta);
                prodL *= cn_term(a.w, b.w, l0 + 3, s_ui, s_uj, theta);
            }
        }
    }

    int lane = tid & 31, w = tid >> 5;
    #pragma unroll
    for (int o = 16; o; o >>= 1)
        prodL *= __shfl_xor_sync(0xffffffffu, prodL, o);
    if (lane == 0) s_red[w] = prodL;
    __syncthreads();

    // dot_k pieces: warp 0 -> theta_k . u_i ; warp 1 -> theta_k . u_j
    if (w < 2) {
        const float* th = theta + (size_t)k * DD;
        const float* u = (w == 0) ? s_ui : s_uj;
        float acc = 0.f;
        #pragma unroll
        for (int d = lane; d < DD; d += 32) acc += u[d] * th[d];
        #pragma unroll
        for (int o = 16; o; o >>= 1)
            acc += __shfl_down_sync(0xffffffffu, acc, o);
        if (lane == 0) { if (w == 0) s_tik = acc; else s_tjk = acc; }
    }
    __syncthreads();

    if (tid == 0) {
        float prodAll = s_red[0];
        #pragma unroll
        for (int x = 1; x < 8; x++) prodAll *= s_red[x];

        float a_ik = __ldg(adj + (size_t)i * NN + k);
        float a_jk = __ldg(adj + (size_t)j * NN + k);
        float dg = g_diag[k];
        float dot_k = a_ik * (dg - s_tik) + a_jk * (dg - s_tjk);

        float ltr = softplus_stable(-dot_k);
        if (c == 1) {
            float C1 = 1.f - prodAll;
            float C0 = (dot_k < -100.f) ? 0.f : 1.f / (1.f + expf(-dot_k));
            ltr += 1.f - C0 / (C1 + EPS_C);
        } else {
            ltr += dot_k;
        }
        atomicAdd(&g_Ltr, ltr);
    }
}

// reads accumulators, writes result, and resets accumulators for the next call
__global__ void final_kernel(float* __restrict__ out) {
    out[0] = g_Lsh + BETA0 * g_Ltr + BETA1 * ((float)SS) * g_sq;
    g_Lsh = 0.f; g_Ltr = 0.f; g_sq = 0.f;
}

extern "C" void kernel_launch(void* const* d_in, const int* in_sizes, int n_in,
                              void* d_out, int out_size) {
    const float* emb_t    = (const float*)d_in[0];
    const float* emb_prev = (const float*)d_in[1];
    const float* theta    = (const float*)d_in[2];
    const float* adj      = (const float*)d_in[3];
    const int*   j_idx    = (const int*)d_in[4];
    const int*   k_idx    = (const int*)d_in[5];
    const int*   negj_idx = (const int*)d_in[6];
    const int*   i_idx    = (const int*)d_in[7];
    const int*   cond     = (const int*)d_in[8];
    float* out = (float*)d_out;

    cudaFuncSetAttribute(ltr_kernel,
                         cudaFuncAttributeMaxDynamicSharedMemorySize, DYN_SMEM);

    prep_kernel<<<NN / 8 + SS / 8, 256>>>(emb_t, emb_prev, theta,
                                          j_idx, k_idx, negj_idx);
    ltr_kernel<<<SS, 256, DYN_SMEM>>>(emb_t, theta, adj, j_idx, k_idx, i_idx, cond);
    final_kernel<<<1, 1>>>(out);
}

// round 4
// speedup vs baseline: 1.5277x; 1.5277x over previous
#include <cuda_runtime.h>
#include <math.h>
#include <stdint.h>

#define NN 8192
#define DD 64
#define SS 4096
#define BETA0 0.1f
#define BETA1 0.1f
#define EPS_C 1e-6f

#define CHUNK_F 2048                      // floats per chunk per row (8 KB)
#define CHUNK_B (CHUNK_F * 4)
#define NCHUNK (NN / CHUNK_F)             // 4 chunk-pairs, all in flight
#define DYN_SMEM (NCHUNK * 2 * CHUNK_B)   // 64 KB

#define SMOOTH_BLKS 128
#define HINGE_BLKS  512                   // 8 samples per block
#define PRE_BLKS (SMOOTH_BLKS + HINGE_BLKS)

__device__ float g_Lsh;
__device__ float g_Ltr;
__device__ float g_sq;

__device__ __forceinline__ float softplus_stable(float x) {
    return fmaxf(x, 0.f) + log1pf(expf(-fabsf(x)));
}

// ---- TMA bulk-copy + mbarrier helpers ----
__device__ __forceinline__ void mbar_init(uint32_t mbar, uint32_t count) {
    asm volatile("mbarrier.init.shared.b64 [%0], %1;" :: "r"(mbar), "r"(count) : "memory");
}
__device__ __forceinline__ void mbar_expect_tx(uint32_t mbar, uint32_t bytes) {
    asm volatile("mbarrier.arrive.expect_tx.shared.b64 _, [%0], %1;"
                 :: "r"(mbar), "r"(bytes) : "memory");
}
__device__ __forceinline__ void bulk_g2s(uint32_t dst_smem, const void* src_gmem,
                                         uint32_t bytes, uint32_t mbar) {
    asm volatile(
        "cp.async.bulk.shared::cluster.global.mbarrier::complete_tx::bytes "
        "[%0], [%1], %2, [%3];"
        :: "r"(dst_smem), "l"(src_gmem), "r"(bytes), "r"(mbar) : "memory");
}
__device__ __forceinline__ void mbar_wait(uint32_t mbar, uint32_t parity) {
    asm volatile(
        "{\n\t"
        ".reg .pred P1;\n\t"
        "WAIT_LOOP_%=:\n\t"
        "mbarrier.try_wait.parity.acquire.cta.shared::cta.b64 P1, [%0], %1, 0x989680;\n\t"
        "@P1 bra.uni WAIT_DONE_%=;\n\t"
        "bra.uni WAIT_LOOP_%=;\n\t"
        "WAIT_DONE_%=:\n\t"
        "}"
        :: "r"(mbar), "r"(parity) : "memory");
}

// (1 - P) for one common neighbor; diag computed on the fly: theta_l . u_l
__device__ __forceinline__ float cn_term(float a, float b, int l,
                                         const float4* __restrict__ s_ui4,
                                         const float4* __restrict__ s_uj4,
                                         const float* __restrict__ theta,
                                         const float* __restrict__ emb_t) {
    const float4* th = (const float4*)(theta + (size_t)l * DD);
    const float4* ul = (const float4*)(emb_t + (size_t)l * DD);
    float tl = 0.f, ti = 0.f, tj = 0.f;
    #pragma unroll
    for (int q = 0; q < DD / 4; q++) {
        float4 t = __ldg(th + q);
        float4 u = __ldg(ul + q);
        float4 vi = s_ui4[q];
        float4 vj = s_uj4[q];
        tl += t.x * u.x  + t.y * u.y  + t.z * u.z  + t.w * u.w;
        ti += t.x * vi.x + t.y * vi.y + t.z * vi.z + t.w * vi.w;
        tj += t.x * vj.x + t.y * vj.y + t.z * vj.z + t.w * vj.w;
    }
    float dot = a * (tl - ti) + b * (tl - tj);
    if (dot < -100.f) return 1.f;
    float P = 1.f / (1.f + expf(-dot));
    return 1.f - P;
}

// ONE kernel: [0,SMOOTH) smooth, [SMOOTH,PRE) hinge, [PRE, PRE+SS) L_tr samples.
// Prep blocks are scheduled first so they hide inside ltr's memory latency.
__global__ void __launch_bounds__(256) fused_kernel(
    const float* __restrict__ emb_t,
    const float* __restrict__ emb_prev,
    const float* __restrict__ theta,
    const float* __restrict__ adj,
    const int* __restrict__ j_idx,
    const int* __restrict__ k_idx,
    const int* __restrict__ negj_idx,
    const int* __restrict__ i_idx,
    const int* __restrict__ cond) {

    extern __shared__ __align__(16) float sbuf[];     // ltr: [NCHUNK][2][CHUNK_F]
    __shared__ alignas(8) unsigned long long smbar[NCHUNK];
    __shared__ float s_ui[DD];
    __shared__ float s_uj[DD];
    __shared__ float s_red[8];
    __shared__ float s_tik, s_tjk, s_dgk;

    int bid = blockIdx.x;
    int tid = threadIdx.x;
    int lane = tid & 31, w = tid >> 5;

    // ================= smooth: sum (emb_t - emb_prev)^2 =================
    if (bid < SMOOTH_BLKS) {
        const float4* et = (const float4*)emb_t;
        const float4* ep = (const float4*)emb_prev;
        const int TOT4 = NN * DD / 4;                 // 131072
        float ssum = 0.f;
        for (int q = bid * 256 + tid; q < TOT4; q += SMOOTH_BLKS * 256) {
            float4 a = __ldg(et + q);
            float4 b = __ldg(ep + q);
            float dx = a.x - b.x, dy = a.y - b.y, dz = a.z - b.z, dw = a.w - b.w;
            ssum += dx * dx + dy * dy + dz * dz + dw * dw;
        }
        #pragma unroll
        for (int o = 16; o; o >>= 1) ssum += __shfl_down_sync(0xffffffffu, ssum, o);
        if (lane == 0) s_red[w] = ssum;
        __syncthreads();
        if (tid == 0) {
            float t = s_red[0];
            #pragma unroll
            for (int x = 1; x < 8; x++) t += s_red[x];
            atomicAdd(&g_sq, t);
        }
        return;
    }
    // ================= triplet hinge =================
    if (bid < PRE_BLKS) {
        int s = (bid - SMOOTH_BLKS) * 8 + w;
        int j = j_idx[s], k = k_idx[s], nj = negj_idx[s];
        const float* uj = emb_t + (size_t)j  * DD;
        const float* uk = emb_t + (size_t)k  * DD;
        const float* un = emb_t + (size_t)nj * DD;
        float pos = 0.f, neg = 0.f;
        #pragma unroll
        for (int d = lane; d < DD; d += 32) {
            float a = uj[d] - uk[d]; pos += a * a;
            float b = un[d] - uk[d]; neg += b * b;
        }
        #pragma unroll
        for (int o = 16; o; o >>= 1) {
            pos += __shfl_down_sync(0xffffffffu, pos, o);
            neg += __shfl_down_sync(0xffffffffu, neg, o);
        }
        float h = pos - neg + 1.0f;
        if (lane == 0) s_red[w] = (h > 0.f) ? h : 0.f;
        __syncthreads();
        if (tid == 0) {
            float t = s_red[0];
            #pragma unroll
            for (int x = 1; x < 8; x++) t += s_red[x];
            if (t != 0.f) atomicAdd(&g_Lsh, t);
        }
        return;
    }
    // ================= L_tr: one block per sample =================
    int s = bid - PRE_BLKS;
    int c = cond[s];
    if (c == -1) return;

    int i = i_idx[s], j = j_idx[s], k = k_idx[s];

    if (tid < DD)          s_ui[tid]      = emb_t[(size_t)i * DD + tid];
    else if (tid < 2*DD)   s_uj[tid - DD] = emb_t[(size_t)j * DD + (tid - DD)];

    uint32_t mb0 = (uint32_t)__cvta_generic_to_shared(&smbar[0]);
    if (c == 1 && tid == 0) {
        #pragma unroll
        for (int cc = 0; cc < NCHUNK; ++cc) mbar_init(mb0 + 8 * cc, 1);
        asm volatile("fence.proxy.async.shared::cta;" ::: "memory");
    }
    __syncthreads();

    float prodL = 1.f;
    if (c == 1) {
        const float* ri = adj + (size_t)i * NN;
        const float* rj = adj + (size_t)j * NN;
        uint32_t sb = (uint32_t)__cvta_generic_to_shared(sbuf);

        if (tid == 0) {
            #pragma unroll
            for (int cc = 0; cc < NCHUNK; ++cc) {
                uint32_t mb = mb0 + 8 * cc;
                uint32_t dst = sb + (uint32_t)cc * 2 * CHUNK_B;
                mbar_expect_tx(mb, 2 * CHUNK_B);
                bulk_g2s(dst,           ri + (size_t)cc * CHUNK_F, CHUNK_B, mb);
                bulk_g2s(dst + CHUNK_B, rj + (size_t)cc * CHUNK_F, CHUNK_B, mb);
            }
        }
        const float4* s_ui4 = (const float4*)s_ui;
        const float4* s_uj4 = (const float4*)s_uj;

        #pragma unroll
        for (int cc = 0; cc < NCHUNK; ++cc) {
            mbar_wait(mb0 + 8 * cc, 0);
            const float4* A = (const float4*)(sbuf + (size_t)cc * 2 * CHUNK_F);
            const float4* B = (const float4*)(sbuf + (size_t)cc * 2 * CHUNK_F + CHUNK_F);
            #pragma unroll
            for (int it = 0; it < CHUNK_F / 4 / 256; ++it) {   // 2 iterations
                int q = tid + it * 256;
                float4 a = A[q];
                float4 b = B[q];
                int l0 = cc * CHUNK_F + q * 4;
                if (a.x > 0.f && b.x > 0.f)
                    prodL *= cn_term(a.x, b.x, l0 + 0, s_ui4, s_uj4, theta, emb_t);
                if (a.y > 0.f && b.y > 0.f)
                    prodL *= cn_term(a.y, b.y, l0 + 1, s_ui4, s_uj4, theta, emb_t);
                if (a.z > 0.f && b.z > 0.f)
                    prodL *= cn_term(a.z, b.z, l0 + 2, s_ui4, s_uj4, theta, emb_t);
                if (a.w > 0.f && b.w > 0.f)
                    prodL *= cn_term(a.w, b.w, l0 + 3, s_ui4, s_uj4, theta, emb_t);
            }
        }
    }

    #pragma unroll
    for (int o = 16; o; o >>= 1)
        prodL *= __shfl_xor_sync(0xffffffffu, prodL, o);
    if (lane == 0) s_red[w] = prodL;
    __syncthreads();

    // warp0: theta_k.u_i ; warp1: theta_k.u_j ; warp2: theta_k.u_k
    if (w < 3) {
        const float* th = theta + (size_t)k * DD;
        const float* u = (w == 0) ? s_ui
                       : (w == 1) ? s_uj
                                  : emb_t + (size_t)k * DD;
        float acc = 0.f;
        #pragma unroll
        for (int d = lane; d < DD; d += 32) acc += u[d] * th[d];
        #pragma unroll
        for (int o = 16; o; o >>= 1)
            acc += __shfl_down_sync(0xffffffffu, acc, o);
        if (lane == 0) {
            if (w == 0) s_tik = acc;
            else if (w == 1) s_tjk = acc;
            else s_dgk = acc;
        }
    }
    __syncthreads();

    if (tid == 0) {
        float prodAll = s_red[0];
        #pragma unroll
        for (int x = 1; x < 8; x++) prodAll *= s_red[x];

        float a_ik = __ldg(adj + (size_t)i * NN + k);
        float a_jk = __ldg(adj + (size_t)j * NN + k);
        float dg = s_dgk;
        float dot_k = a_ik * (dg - s_tik) + a_jk * (dg - s_tjk);

        float ltr = softplus_stable(-dot_k);
        if (c == 1) {
            float C1 = 1.f - prodAll;
            float C0 = (dot_k < -100.f) ? 0.f : 1.f / (1.f + expf(-dot_k));
            ltr += 1.f - C0 / (C1 + EPS_C);
        } else {
            ltr += dot_k;
        }
        atomicAdd(&g_Ltr, ltr);
    }
}

// reads accumulators, writes result, resets accumulators for the next replay
__global__ void final_kernel(float* __restrict__ out) {
    out[0] = g_Lsh + BETA0 * g_Ltr + BETA1 * ((float)SS) * g_sq;
    g_Lsh = 0.f; g_Ltr = 0.f; g_sq = 0.f;
}

extern "C" void kernel_launch(void* const* d_in, const int* in_sizes, int n_in,
                              void* d_out, int out_size) {
    const float* emb_t    = (const float*)d_in[0];
    const float* emb_prev = (const float*)d_in[1];
    const float* theta    = (const float*)d_in[2];
    const float* adj      = (const float*)d_in[3];
    const int*   j_idx    = (const int*)d_in[4];
    const int*   k_idx    = (const int*)d_in[5];
    const int*   negj_idx = (const int*)d_in[6];
    const int*   i_idx    = (const int*)d_in[7];
    const int*   cond     = (const int*)d_in[8];
    float* out = (float*)d_out;

    cudaFuncSetAttribute(fused_kernel,
                         cudaFuncAttributeMaxDynamicSharedMemorySize, DYN_SMEM);

    fused_kernel<<<PRE_BLKS + SS, 256, DYN_SMEM>>>(
        emb_t, emb_prev, theta, adj, j_idx, k_idx, negj_idx, i_idx, cond);
    final_kernel<<<1, 1>>>(out);
}